// round 11
// baseline (speedup 1.0000x reference)
#include <cuda_runtime.h>

#define SB 2048
#define TB 64
#define NB 256
#define NBLK 64      // 64 blocks x 4 warps = 256 chains, one warp per chain, one block per SM
#define PF 8         // emission prefetch depth (steps)

typedef unsigned long long ull;

__device__ float g_part[NB];
__device__ unsigned int g_cnt;   // zero-init; reset by last block each run

static __device__ __forceinline__ ull pk2(float a, float b) {
    ull r; asm("mov.b64 %0,{%1,%2};" : "=l"(r) : "f"(a), "f"(b)); return r;
}
static __device__ __forceinline__ void upk2(ull v, float& a, float& b) {
    asm("mov.b64 {%0,%1},%2;" : "=f"(a), "=f"(b) : "l"(v));
}
static __device__ __forceinline__ ull fma2(ull a, ull b, ull c) {
    ull d; asm("fma.rn.f32x2 %0,%1,%2,%3;" : "=l"(d) : "l"(a), "l"(b), "l"(c)); return d;
}
static __device__ __forceinline__ ull add2(ull a, ull b) {
    ull d; asm("add.rn.f32x2 %0,%1,%2;" : "=l"(d) : "l"(a), "l"(b)); return d;
}
static __device__ __forceinline__ ull mul2(ull a, ull b) {
    ull d; asm("mul.rn.f32x2 %0,%1,%2;" : "=l"(d) : "l"(a), "l"(b)); return d;
}

__global__ __launch_bounds__(128, 1) void crf_warp_kernel(
    const float* __restrict__ emis,     // (B, S, T)
    const float* __restrict__ startT,   // (T)
    const float* __restrict__ endT,     // (T)
    const float* __restrict__ trans,    // (T, T)
    const int*   __restrict__ tags,     // (B, S)
    const int*   __restrict__ maskp,    // (B, S)
    float*       __restrict__ out)
{
    const int tid  = threadIdx.x;
    const int w    = tid >> 5;          // chain within block (one warp per chain)
    const int lane = tid & 31;
    const int b    = blockIdx.x * 4 + w;
    const int j0   = lane * 2;          // owned states j0, j0+1

    const float* __restrict__ em = emis + (size_t)b * SB * TB;
    const int*   __restrict__ tg = tags  + b * SB;
    const int*   __restrict__ mk = maskp + b * SB;

    __shared__ __align__(16) float p[4][2][TB];  // [chain][parity][state]
    __shared__ float sred[4];
    __shared__ int   lastflag;

    // ---------------- numerator: gold tag path (warp-parallel over steps) ----------
    float nacc = 0.f;
    int   macc = 0;
    for (int t = lane; t < SB; t += 32) {
        int m = mk[t];
        macc += m;
        if (t > 0 && m) {
            int tp = tg[t - 1], tc = tg[t];
            nacc += trans[tp * TB + tc] + em[t * TB + tc];
        }
    }
    if (lane == 0) nacc += startT[tg[0]] + em[tg[0]];
    #pragma unroll
    for (int o = 16; o; o >>= 1) {
        nacc += __shfl_down_sync(0xffffffffu, nacc, o);
        macc += __shfl_down_sync(0xffffffffu, macc, o);
    }
    // lane 0 now holds numerator partial (nacc) and mask sum (macc)

    // ---------------- E = exp(transitions): packed i-pairs for both owned states ---
    // E0[m] = (exp T[2m][j0],   exp T[2m+1][j0])
    // E1[m] = (exp T[2m][j0+1], exp T[2m+1][j0+1])
    ull E0[32], E1[32];
    #pragma unroll
    for (int m = 0; m < 32; m++) {
        float2 r0 = *(const float2*)(trans + (2 * m) * TB + j0);
        float2 r1 = *(const float2*)(trans + (2 * m + 1) * TB + j0);
        E0[m] = pk2(expf(r0.x), expf(r1.x));
        E1[m] = pk2(expf(r0.y), expf(r1.y));
    }

    // ---------------- init: p = exp(start + em0), cr seed = 1 ----------------------
    float2 st = *(const float2*)(startT + j0);
    float2 e0 = *(const float2*)(em + j0);
    ull pq = pk2(__expf(st.x + e0.x), __expf(st.y + e0.y));
    ((ull*)p[w][0])[lane] = pq;
    float s0prev = 1.0f;

    // prefetch ring (depth PF): exp(emissions) precomputed off critical path
    ull eemr[PF];
    int mkr[PF];
    #pragma unroll
    for (int k = 0; k < PF; k++) {
        int t = 1 + k;
        float2 e = *(const float2*)(em + t * TB + j0);
        eemr[k] = pk2(__expf(e.x), __expf(e.y));
        mkr[k]  = mk[t];
    }

    double Mtot = 0.0;   // flushed from fp32 window every PF steps
    float  win  = 0.f;

    // ---------------- forward recursion: warp-private, one syncwarp per step -------
    #pragma unroll 1
    for (int tb = 1; tb < SB; tb += PF) {
        #pragma unroll
        for (int k = 0; k < PF; k++) {
            const int t = tb + k;
            if (t >= SB) break;            // uniform
            const int rb = k & 1;          // (t-1)&1, tb odd
            const int wb = rb ^ 1;

            __syncwarp();

            // normalizer path — hidden under the dot
            float cr  = __shfl_sync(0xffffffffu, s0prev, 0);
            float inv = __fdividef(1.0f, cr);
            ull wpre  = mul2(eemr[k], pk2(inv, inv));

            // dot: s_j = sum_i p_i * E[i][j] for j0 and j0+1
            const ulonglong2* __restrict__ pv = (const ulonglong2*)p[w][rb];
            ull a0 = 0, a1 = 0, a2 = 0, a3 = 0;   // state j0
            ull c0 = 0, c1 = 0, c2 = 0, c3 = 0;   // state j0+1
            #pragma unroll
            for (int i = 0; i < 8; i++) {
                ulonglong2 v0 = pv[2 * i];
                a0 = fma2(v0.x, E0[4 * i + 0], a0);
                c0 = fma2(v0.x, E1[4 * i + 0], c0);
                a1 = fma2(v0.y, E0[4 * i + 1], a1);
                c1 = fma2(v0.y, E1[4 * i + 1], c1);
                ulonglong2 v1 = pv[2 * i + 1];
                a2 = fma2(v1.x, E0[4 * i + 2], a2);
                c2 = fma2(v1.x, E1[4 * i + 2], c2);
                a3 = fma2(v1.y, E0[4 * i + 3], a3);
                c3 = fma2(v1.y, E1[4 * i + 3], c3);
            }
            ull sa = add2(add2(a0, a1), add2(a2, a3));
            ull sc = add2(add2(c0, c1), add2(c2, c3));
            float sa0, sa1, sc0, sc1;
            upk2(sa, sa0, sa1);
            upk2(sc, sc0, sc1);
            float s_0 = sa0 + sa1;          // raw sum, state j0
            float s_1 = sc0 + sc1;          // raw sum, state j0+1

            ull qn = mul2(pk2(s_0, s_1), wpre);
            ull q  = mkr[k] ? qn : pq;      // masked step: alpha unchanged
            pq = q;
            ((ull*)p[w][wb])[lane] = q;
            s0prev = s_0;                   // lane 0's value seeds next normalizer
            if (mkr[k]) win += __logf(cr);  // side chain

            // prefetch t+PF
            if (t + PF < SB) {
                float2 e = *(const float2*)(em + (t + PF) * TB + j0);
                eemr[k] = pk2(__expf(e.x), __expf(e.y));
                mkr[k]  = mk[t + PF];
            }
        }
        Mtot += (double)win;
        win = 0.f;
    }

    // ---------------- finish: den = M + log(sum_j p_j * exp(endT_j)) ---------------
    float q0, q1;
    upk2(pq, q0, q1);                       // final alpha lives in registers
    float2 et = *(const float2*)(endT + j0);
    float term = q0 * __expf(et.x) + q1 * __expf(et.y);
    #pragma unroll
    for (int o = 16; o; o >>= 1)
        term += __shfl_down_sync(0xffffffffu, term, o);

    if (lane == 0) {
        float den = (float)(Mtot + (double)logf(term));
        int   se  = macc - 1;
        float num = nacc + endT[tg[se]];
        g_part[b] = den - num;
    }

    // ---------------- fused grid reduction: last block computes the mean -----------
    __syncthreads();
    if (tid == 0) {
        __threadfence();
        unsigned int old = atomicAdd(&g_cnt, 1u);
        lastflag = (old == NBLK - 1);
    }
    __syncthreads();
    if (lastflag) {
        __threadfence();
        float v = g_part[tid] + g_part[tid + 128];
        #pragma unroll
        for (int o = 16; o; o >>= 1)
            v += __shfl_down_sync(0xffffffffu, v, o);
        if (lane == 0) sred[w] = v;
        __syncthreads();
        if (tid == 0) {
            float ssum = sred[0] + sred[1] + sred[2] + sred[3];
            out[0] = ssum / (float)NB;   // mean(den - num)
            g_cnt = 0;                    // reset for next replay
        }
    }
}

extern "C" void kernel_launch(void* const* d_in, const int* in_sizes, int n_in,
                              void* d_out, int out_size) {
    const float* emissions = (const float*)d_in[0];
    const float* startT    = (const float*)d_in[1];
    const float* endT      = (const float*)d_in[2];
    const float* trans     = (const float*)d_in[3];
    const int*   tags      = (const int*)d_in[4];
    const int*   mask      = (const int*)d_in[5];
    (void)in_sizes; (void)n_in; (void)out_size;

    crf_warp_kernel<<<NBLK, 128>>>(emissions, startT, endT, trans, tags, mask,
                                   (float*)d_out);
}

// round 12
// speedup vs baseline: 3.2251x; 3.2251x over previous
#include <cuda_runtime.h>

#define SB 2048
#define TB 64
#define NB 256
#define NBLK 128     // 2 chains per block, 2 warps per chain -> 1 warp per SMSP
#define PF 8         // emission prefetch depth (steps)

typedef unsigned long long ull;

__device__ float g_part[NB];
__device__ unsigned int g_cnt;   // zero-init; reset by last block each run

static __device__ __forceinline__ ull pk2(float a, float b) {
    ull r; asm("mov.b64 %0,{%1,%2};" : "=l"(r) : "f"(a), "f"(b)); return r;
}
static __device__ __forceinline__ void upk2(ull v, float& a, float& b) {
    asm("mov.b64 {%0,%1},%2;" : "=f"(a), "=f"(b) : "l"(v));
}
static __device__ __forceinline__ ull fma2(ull a, ull b, ull c) {
    ull d; asm("fma.rn.f32x2 %0,%1,%2,%3;" : "=l"(d) : "l"(a), "l"(b), "l"(c)); return d;
}
static __device__ __forceinline__ ull add2(ull a, ull b) {
    ull d; asm("add.rn.f32x2 %0,%1,%2;" : "=l"(d) : "l"(a), "l"(b)); return d;
}
static __device__ __forceinline__ void barx(int id) {
    asm volatile("bar.sync %0, 64;" :: "r"(id) : "memory");
}

__global__ __launch_bounds__(128, 1) void crf_main_kernel(
    const float* __restrict__ emis,     // (B, S, T)
    const float* __restrict__ startT,   // (T)
    const float* __restrict__ endT,     // (T)
    const float* __restrict__ trans,    // (T, T)
    const int*   __restrict__ tags,     // (B, S)
    const int*   __restrict__ maskp,    // (B, S)
    float*       __restrict__ out)
{
    const int tid  = threadIdx.x;
    const int w    = tid >> 5;
    const int lane = tid & 31;
    const int c    = w >> 1;                // chain in block: warps {2c, 2c+1} -> SMSPs {2c,2c+1}
    const int jh   = w & 1;                 // state-vector half
    const int j    = (jh << 5) | lane;      // owned state 0..63
    const int b    = blockIdx.x * 2 + c;
    const int barid = c + 1;

    const float* __restrict__ em = emis + (size_t)b * SB * TB;
    const int*   __restrict__ tg = tags  + b * SB;
    const int*   __restrict__ mk = maskp + b * SB;

    __shared__ __align__(16) float p[2][2][TB];  // [chain][parity][state]
    __shared__ float craw[2][2];                 // [chain][parity] normalizer seed
    __shared__ float nred[2][2];                 // numerator partial per (chain, warp)
    __shared__ int   mred[2][2];
    __shared__ float red[2][2];
    __shared__ float sred[4];
    __shared__ int   lastflag;

    // ---------------- numerator: gold tag path (64-way parallel per chain) ----------
    float nacc = 0.f;
    int   macc = 0;
    for (int t = j; t < SB; t += TB) {
        int m = mk[t];
        macc += m;
        if (t > 0 && m) {
            int tp = tg[t - 1], tc = tg[t];
            nacc += trans[tp * TB + tc] + em[t * TB + tc];
        }
    }
    if (j == 0) nacc += startT[tg[0]] + em[tg[0]];
    #pragma unroll
    for (int o = 16; o; o >>= 1) {
        nacc += __shfl_down_sync(0xffffffffu, nacc, o);
        macc += __shfl_down_sync(0xffffffffu, macc, o);
    }
    if (lane == 0) { nred[c][jh] = nacc; mred[c][jh] = macc; }

    // ---------------- E = exp(transitions) column j into registers -----------------
    ull Ecol[TB / 2];
    #pragma unroll
    for (int i = 0; i < TB / 2; i++) {
        float e0 = expf(trans[(2 * i) * TB + j]);
        float e1 = expf(trans[(2 * i + 1) * TB + j]);
        Ecol[i] = pk2(e0, e1);
    }

    // ---------------- init: p = exp(start + em0) -----------------------------------
    float pq = __expf(startT[j] + em[j]);
    p[c][0][j] = pq;
    if (j == 0) craw[c][0] = 1.0f;

    // prefetch ring, distance PF: RAW emissions (exp applied at use time, 8 steps later)
    float emr[PF];
    int   mkr[PF];
    #pragma unroll
    for (int k = 0; k < PF; k++) {
        int t = 1 + k;
        emr[k] = em[t * TB + j];
        mkr[k] = mk[t];
    }

    // log-offset as a renormalized product: Mtot = Eacc*ln2 + log(P) at the end
    float P    = 1.0f;
    int   Eacc = 0;

    // ---------------- forward recursion ---------------------------------------------
    #pragma unroll 1
    for (int tb = 1; tb < SB; tb += PF) {
        #pragma unroll
        for (int k = 0; k < PF; k++) {
            const int t = tb + k;
            const int rb = k & 1;        // read parity ((t-1)&1; tb odd)
            const int wb = rb ^ 1;

            barx(barid);

            // independent of the dot — all hidden under FFMA issue
            float eem = __expf(emr[k]);            // emission exp (loaded 8 steps ago)
            float cr  = craw[c][rb];
            float inv = __fdividef(1.0f, cr);

            // dot: s_j = sum_i p[i] * E[i][j]  (16x broadcast LDS.128, 32x FFMA2)
            const ulonglong2* __restrict__ pv = (const ulonglong2*)p[c][rb];
            ull a0 = 0ull, a1 = 0ull, a2 = 0ull, a3 = 0ull;
            #pragma unroll
            for (int i = 0; i < 16; i += 4) {
                ulonglong2 v0 = pv[i + 0];
                a0 = fma2(v0.x, Ecol[2 * i + 0], a0);
                a1 = fma2(v0.y, Ecol[2 * i + 1], a1);
                ulonglong2 v1 = pv[i + 1];
                a2 = fma2(v1.x, Ecol[2 * i + 2], a2);
                a3 = fma2(v1.y, Ecol[2 * i + 3], a3);
                ulonglong2 v2 = pv[i + 2];
                a0 = fma2(v2.x, Ecol[2 * i + 4], a0);
                a1 = fma2(v2.y, Ecol[2 * i + 5], a1);
                ulonglong2 v3 = pv[i + 3];
                a2 = fma2(v3.x, Ecol[2 * i + 6], a2);
                a3 = fma2(v3.y, Ecol[2 * i + 7], a3);
            }
            ull sa = add2(add2(a0, a1), add2(a2, a3));
            float s0, s1; upk2(sa, s0, s1);
            float s = s0 + s1;

            float q = mkr[k] ? s * (eem * inv) : pq;  // alpha' = M + log(cr) + log q
            pq = q;
            p[c][wb][j] = q;
            if (j == 0) craw[c][wb] = s;

            // side chain: accumulate log(cr) as exponent + mantissa product (ALU only)
            float crm = mkr[k] ? cr : 1.0f;
            P *= crm;
            int u = __float_as_int(P);
            Eacc += (u >> 23) - 127;
            P = __int_as_float((u & 0x807fffff) | 0x3f800000);

            // prefetch t+PF (raw load only — no dependent math)
            if (t + PF < SB) {
                emr[k] = em[(t + PF) * TB + j];
                mkr[k] = mk[t + PF];
            }
        }
    }

    // ---------------- finish: den = M + log(sum_j p_j * exp(endT_j)) ---------------
    float term = pq * __expf(endT[j]);       // final alpha lives in pq
    #pragma unroll
    for (int o = 16; o; o >>= 1)
        term += __shfl_down_sync(0xffffffffu, term, o);
    if (lane == 0) red[c][jh] = term;
    barx(barid);

    if (j == 0) {
        double Mtot = (double)Eacc * 0.6931471805599453 + (double)logf(P);
        float total = red[c][0] + red[c][1];
        float den = (float)(Mtot + (double)logf(total));
        float num = nred[c][0] + nred[c][1];
        int   se  = mred[c][0] + mred[c][1] - 1;
        num += endT[tg[se]];
        g_part[b] = den - num;
    }

    // ---------------- fused grid reduction: last block computes the mean -----------
    __syncthreads();
    if (tid == 0) {
        __threadfence();
        unsigned int old = atomicAdd(&g_cnt, 1u);
        lastflag = (old == NBLK - 1);
    }
    __syncthreads();
    if (lastflag) {
        __threadfence();
        float v = g_part[tid] + g_part[tid + 128];
        #pragma unroll
        for (int o = 16; o; o >>= 1)
            v += __shfl_down_sync(0xffffffffu, v, o);
        if (lane == 0) sred[w] = v;
        __syncthreads();
        if (tid == 0) {
            float ssum = sred[0] + sred[1] + sred[2] + sred[3];
            out[0] = ssum / (float)NB;   // mean(den - num)
            g_cnt = 0;                    // reset for next replay
        }
    }
}

extern "C" void kernel_launch(void* const* d_in, const int* in_sizes, int n_in,
                              void* d_out, int out_size) {
    const float* emissions = (const float*)d_in[0];
    const float* startT    = (const float*)d_in[1];
    const float* endT      = (const float*)d_in[2];
    const float* trans     = (const float*)d_in[3];
    const int*   tags      = (const int*)d_in[4];
    const int*   mask      = (const int*)d_in[5];
    (void)in_sizes; (void)n_in; (void)out_size;

    crf_main_kernel<<<NBLK, 128>>>(emissions, startT, endT, trans, tags, mask,
                                   (float*)d_out);
}